// round 4
// baseline (speedup 1.0000x reference)
#include <cuda_runtime.h>
#include <math.h>

// ResidualVQ fused kernel for B200 (sm_100a).
// x: (32, 512, 1024) fp32, codebooks: (6, 1024, 512) fp32.
//
// Pass 1: fast FFMA2 GEMM distance nominates per-token top-2 candidates.
// Decision replica: distances of the two candidates are recomputed with
// bit-replicas of the reference pipeline:
//   dot : cuBLAS SIMT SGEMM = serial ascending-k FFMA chain (fp32)
//   Rn  : XLA row-reduce of r*r   (lane-strided serial + shfl tree), fp32
//   cn  : XLA row-reduce of cb*cb (same pattern), fp32
//   dist: fl32( fl32( Rn - fl32(2*dot) ) + cn ), first-index tie-break
// Residual update replicates the reference STE rounding:
//   t = fl(xd - r); quant = fl(r + t); r_new = fl(r - quant)

#define QL      6
#define KCODES  1024
#define CD      512
#define TT      1024
#define NBATCH  32
#define NTOK    (NBATCH * TT)       // 32768
#define TILE_T  64
#define NBLK    (NTOK / TILE_T)     // 512
#define KC      64                  // c-phase width
#define NPH     (CD / KC)           // 8 phases
#define CCHUNK  128                 // codes per chunk
#define BSTRIDE 130                 // floats per Bs row (128 dup-pairs + pad)
#define OUT_ELEMS (NBATCH * CD * TT)
#define SMEM_BYTES ((CD*TILE_T + CCHUNK*BSTRIDE + TILE_T + TILE_T + 8) * 4)
#define MARGIN  0.03f

__device__ float g_cbnorm[QL * KCODES];
__device__ int   g_hist[QL * KCODES];
__device__ float g_losspart[QL * NBLK];

union U2 { unsigned long long u; float2 f; };

__device__ __forceinline__ void ffma2(unsigned long long& d,
                                      unsigned long long a,
                                      unsigned long long b) {
    // packed dual-fp32 FMA: d = a*b + d (elementwise on two f32 lanes)
    asm("fma.rn.f32x2 %0, %1, %2, %0;" : "+l"(d) : "l"(a), "l"(b));
}

__global__ void zero_hist_kernel() {
    int i = blockIdx.x * blockDim.x + threadIdx.x;
    if (i < QL * KCODES) g_hist[i] = 0;
}

// ||cb_row||^2 replicating XLA's warp row-reduction:
// lane l serially sums squares of elements l, l+32, ..., then shfl-down tree.
__global__ void cbnorm_kernel(const float* __restrict__ cb) {
    int w    = (blockIdx.x * blockDim.x + threadIdx.x) >> 5;
    int lane = threadIdx.x & 31;
    if (w >= QL * KCODES) return;
    const float* row = cb + (size_t)w * CD;
    float a = 0.f;
    #pragma unroll
    for (int i = 0; i < CD / 32; i++) {
        float v = row[lane + 32 * i];
        a = __fadd_rn(a, __fmul_rn(v, v));
    }
    #pragma unroll
    for (int o = 16; o; o >>= 1)
        a = __fadd_rn(a, __shfl_down_sync(0xffffffffu, a, o));
    if (lane == 0) g_cbnorm[w] = a;
}

// XLA-replica row norm of one token's residual column in As.
// Simulates: 32 lanes, lane l serially adds squares of c = l+32i (i asc),
// then the shfl-down(16,8,4,2,1) tree, all fp32 rn.
__device__ __forceinline__ float xla_rownorm_tok(const float* __restrict__ As,
                                                 int tok) {
    float p[32];
    #pragma unroll
    for (int l = 0; l < 32; l++) {
        float a = 0.f;
        #pragma unroll
        for (int i = 0; i < 16; i++) {
            float r = As[(l + 32 * i) * TILE_T + tok];
            a = __fadd_rn(a, __fmul_rn(r, r));
        }
        p[l] = a;
    }
    #pragma unroll
    for (int o = 16; o; o >>= 1)
        #pragma unroll
        for (int l = 0; l < o; l++) p[l] = __fadd_rn(p[l], p[l + o]);
    return p[0];
}

// 64 FFMA2 steps of the dot accumulation for one c-phase.
__device__ __forceinline__ void dot_phase(U2 (&acc)[2][8],
                                          const float* __restrict__ Ab,
                                          const float* __restrict__ Bs,
                                          int col) {
    #pragma unroll 16
    for (int kk = 0; kk < KC; kk++) {
        unsigned long long a0 = *(const unsigned long long*)(Ab + kk * TILE_T);
        unsigned long long a1 = *(const unsigned long long*)(Ab + kk * TILE_T + 2);
        #pragma unroll
        for (int j = 0; j < 8; j++) {
            unsigned long long bv = *(const unsigned long long*)
                &Bs[(col + 16 * j) * BSTRIDE + 2 * kk];
            ffma2(acc[0][j].u, a0, bv);
            ffma2(acc[1][j].u, a1, bv);
        }
    }
}

// Insert candidate (v, code) into running top-2 (lex order, lower idx first).
__device__ __forceinline__ void top2_insert(float v, int code,
                                            float& v1, int& i1,
                                            float& v2, int& i2) {
    if (v < v1) { v2 = v1; i2 = i1; v1 = v; i1 = code; }
    else if (v < v2) { v2 = v; i2 = code; }
}

// Main fused kernel: 1 CTA = 64 tokens, all 6 quantizer layers.
// Residual lives in smem As[c][token] (fp32, 128 KB).
// Thread map (256 threads): g = tx>>4 (token group: tokens 4g..4g+3),
//                           col = tx&15 (code column: codes col+16j, j=0..7).
__global__ __launch_bounds__(256, 1)
void vq_main_kernel(const float* __restrict__ x, const float* __restrict__ cb,
                    float* __restrict__ out) {
    extern __shared__ float smem[];
    float* As   = smem;                          // [512][64]
    float* Bs   = smem + CD * TILE_T;            // [128][BSTRIDE] dup pairs
    int*   idxs = (int*)(Bs + CCHUNK * BSTRIDE); // [64]
    float* Rn_s = (float*)(idxs + TILE_T);       // [64] per-token ||r||^2 (XLA replica)

    const int tx  = threadIdx.x;
    const int blk = blockIdx.x;
    const int n   = blk >> 4;
    const int t0  = (blk & 15) << 6;
    const float* xblk = x + (size_t)n * CD * TT + t0;

    // Load x tile transposed into As[c][tok]; coalesced over tok.
    {
        const int tok = tx & 63, c0 = tx >> 6;
        for (int k = 0; k < CD / 4; k++) {
            int c = c0 + k * 4;
            As[c * TILE_T + tok] = xblk[c * TT + tok];
        }
    }
    __syncthreads();

    const int g   = tx >> 4;
    const int col = tx & 15;
    const int ccl = col * 4;
    const int tokm = tx >> 2, q4 = tx & 3;   // map for update pass

    // Initial ||r||^2 per token (XLA replica, fp32).
    if (tx < TILE_T) Rn_s[tx] = xla_rownorm_tok(As, tx);
    __syncthreads();

    for (int q = 0; q < QL; q++) {
        const float* cbq = cb + (size_t)q * KCODES * CD;
        const float* cnq = g_cbnorm + q * KCODES;
        float minv[4]  = {3.4e38f, 3.4e38f, 3.4e38f, 3.4e38f};
        float min2v[4] = {3.4e38f, 3.4e38f, 3.4e38f, 3.4e38f};
        int   mini[4]  = {0, 0, 0, 0};
        int   min2i[4] = {1, 1, 1, 1};
        const float Rn0 = Rn_s[4*g+0], Rn1 = Rn_s[4*g+1];
        const float Rn2 = Rn_s[4*g+2], Rn3 = Rn_s[4*g+3];

        for (int ch = 0; ch < KCODES / CCHUNK; ch++) {
            const int k0 = ch * CCHUNK;
            U2 accE[2][8], accO[2][8];
            #pragma unroll
            for (int p = 0; p < 2; p++)
                #pragma unroll
                for (int j = 0; j < 8; j++) { accE[p][j].u = 0ull; accO[p][j].u = 0ull; }

            // Register prefetch of first B phase (this thread's 8 float4s).
            float4 pf[8];
            #pragma unroll
            for (int r = 0; r < 8; r++)
                pf[r] = *(const float4*)&cbq[(size_t)(k0 + g + 16 * r) * CD + ccl];

            for (int ph = 0; ph < NPH; ph++) {
                __syncthreads();  // prior compute done before overwriting Bs
                #pragma unroll
                for (int r = 0; r < 8; r++) {
                    float* dst = Bs + (g + 16 * r) * BSTRIDE + 2 * ccl;
                    float4 v = pf[r];
                    ((float2*)dst)[0] = make_float2(v.x, v.x);
                    ((float2*)dst)[1] = make_float2(v.y, v.y);
                    ((float2*)dst)[2] = make_float2(v.z, v.z);
                    ((float2*)dst)[3] = make_float2(v.w, v.w);
                }
                __syncthreads();
                if (ph < NPH - 1) {   // prefetch next phase, hidden by compute
                    #pragma unroll
                    for (int r = 0; r < 8; r++)
                        pf[r] = *(const float4*)&cbq[(size_t)(k0 + g + 16 * r) * CD +
                                                     (ph + 1) * KC + ccl];
                }
                const float* Ab = As + ph * KC * TILE_T + 4 * g;
                if (ph & 1) dot_phase(accO, Ab, Bs, col);
                else        dot_phase(accE, Ab, Bs, col);
            }
            // Chunk epilogue: approx dist = (Rn - 2*dot) + cn ; running top-2.
            #pragma unroll
            for (int j = 0; j < 8; j++) {
                const int code = k0 + col + 16 * j;
                const float cn = cnq[code];
                float d, v;
                d = accE[0][j].f.x + accO[0][j].f.x;
                v = (Rn0 - 2.f * d) + cn;
                top2_insert(v, code, minv[0], mini[0], min2v[0], min2i[0]);
                d = accE[0][j].f.y + accO[0][j].f.y;
                v = (Rn1 - 2.f * d) + cn;
                top2_insert(v, code, minv[1], mini[1], min2v[1], min2i[1]);
                d = accE[1][j].f.x + accO[1][j].f.x;
                v = (Rn2 - 2.f * d) + cn;
                top2_insert(v, code, minv[2], mini[2], min2v[2], min2i[2]);
                d = accE[1][j].f.y + accO[1][j].f.y;
                v = (Rn3 - 2.f * d) + cn;
                top2_insert(v, code, minv[3], mini[3], min2v[3], min2i[3]);
            }
        }

        // Cross-thread top-2 merge over the 16 code columns (lex: lower idx).
        #pragma unroll
        for (int i = 0; i < 4; i++) {
            float v1 = minv[i], v2 = min2v[i];
            int   i1 = mini[i], i2 = min2i[i];
            #pragma unroll
            for (int o = 8; o; o >>= 1) {
                float w1 = __shfl_down_sync(0xffffffffu, v1, o, 16);
                int   j1 = __shfl_down_sync(0xffffffffu, i1, o, 16);
                float w2 = __shfl_down_sync(0xffffffffu, v2, o, 16);
                int   j2 = __shfl_down_sync(0xffffffffu, i2, o, 16);
                if (w1 < v1 || (w1 == v1 && j1 < i1)) {
                    v2 = v1; i2 = i1;                    // old min1 -> min2 cand
                    if (w2 < v2 || (w2 == v2 && j2 < i2)) { v2 = w2; i2 = j2; }
                    v1 = w1; i1 = j1;
                } else {
                    if (w1 < v2 || (w1 == v2 && j1 < i2)) { v2 = w1; i2 = j1; }
                }
            }
            if (col == 0) {
                int id = i1;
                if (v2 - v1 < MARGIN) {
                    // Reference-replica rescore of the two candidates:
                    // cuBLAS-style serial ascending-k FFMA dot, then the
                    // reference's fp32 rounding grid; first-index tie-break.
                    const int tok = 4 * g + i;
                    const float Rn = Rn_s[tok];
                    const float* ra = cbq + (size_t)i1 * CD;
                    const float* rb = cbq + (size_t)i2 * CD;
                    float ma = 0.f, mb = 0.f;
                    #pragma unroll 8
                    for (int c = 0; c < CD; c++) {
                        float r = As[c * TILE_T + tok];
                        ma = __fmaf_rn(r, ra[c], ma);
                        mb = __fmaf_rn(r, rb[c], mb);
                    }
                    float va = __fadd_rn(__fsub_rn(Rn, __fmul_rn(2.f, ma)),
                                         cnq[i1]);
                    float vb = __fadd_rn(__fsub_rn(Rn, __fmul_rn(2.f, mb)),
                                         cnq[i2]);
                    if (vb < va || (vb == va && i2 < i1)) id = i2;
                }
                idxs[4 * g + i] = id;
                atomicAdd(&g_hist[q * KCODES + id], 1);
            }
        }
        __syncthreads();

        // Residual update replicating the reference STE rounding:
        // t = fl(xd - r); quant = fl(r + t); r_new = fl(r - quant)
        {
            const float* row = cbq + (size_t)idxs[tokm] * CD;
            for (int k = 0; k < CD / 16; k++) {
                const int c = k * 16 + q4 * 4;
                float4 w = *(const float4*)&row[c];
                #pragma unroll
                for (int e = 0; e < 4; e++) {
                    float xd = (&w.x)[e];
                    float* p = &As[(c + e) * TILE_T + tokm];
                    float r = *p;
                    float t = __fsub_rn(xd, r);
                    float quant = __fadd_rn(r, t);
                    *p = __fsub_rn(r, quant);
                }
            }
        }
        __syncthreads();

        // New ||r||^2 per token (XLA replica) — feeds next layer + loss.
        if (tx < TILE_T) Rn_s[tx] = xla_rownorm_tok(As, tx);
        __syncthreads();

        // Loss partial for this layer: sum of Rn over the tile's 64 tokens.
        if (tx < 32) {
            float s = Rn_s[tx] + Rn_s[tx + 32];
            #pragma unroll
            for (int o = 16; o; o >>= 1) s += __shfl_down_sync(0xffffffffu, s, o);
            if (tx == 0) g_losspart[q * NBLK + blk] = s;
        }
        __syncthreads();
    }

    // out = x - residual_final, transposed back; coalesced over tok.
    // (Value differs from the reference's serial quant-sum only at ~1e-7 rel.)
    {
        const int tok = tx & 63, c0 = tx >> 6;
        float* oblk = out + (size_t)n * CD * TT + t0;
        for (int k = 0; k < CD / 4; k++) {
            int c = c0 + k * 4;
            oblk[c * TT + tok] = xblk[c * TT + tok] - As[c * TILE_T + tok];
        }
    }
}

__device__ float block_reduce_512(float v, float* sh) {
    int t = threadIdx.x;
    #pragma unroll
    for (int o = 16; o; o >>= 1) v += __shfl_down_sync(0xffffffffu, v, o);
    if ((t & 31) == 0) sh[t >> 5] = v;
    __syncthreads();
    float r = 0.f;
    if (t < 16) {
        r = sh[t];
        #pragma unroll
        for (int o = 8; o; o >>= 1) r += __shfl_down_sync(0x0000ffffu, r, o, 16);
    }
    __syncthreads();
    return r;   // valid on thread 0
}

__global__ void finalize_kernel(float* __restrict__ out, int out_size) {
    __shared__ float sh[16];
    const int t = threadIdx.x;  // 512 threads

    float ls = 0.f;
    for (int i = t; i < QL * NBLK; i += 512) ls += g_losspart[i];
    ls = block_reduce_512(ls, sh);
    float lossval = ls / ((float)NTOK * (float)CD * (float)QL);

    float ptot = 0.f;
    for (int q = 0; q < QL; q++) {
        float s = 0.f;
        for (int k = t; k < KCODES; k += 512) {
            float p = (float)g_hist[q * KCODES + k] * (1.0f / 32768.0f);
            s += p * logf(p + 1e-7f);
        }
        s = block_reduce_512(s, sh);
        if (t == 0) ptot += expf(-s);
    }
    if (t == 0) {
        if (out_size >= OUT_ELEMS + 2) {
            out[OUT_ELEMS]     = lossval;
            out[OUT_ELEMS + 1] = ptot / (float)QL;
        } else if (out_size == OUT_ELEMS + 1) {
            out[OUT_ELEMS] = lossval;
        }
    }
}

extern "C" void kernel_launch(void* const* d_in, const int* in_sizes, int n_in,
                              void* d_out, int out_size) {
    const float* x  = (const float*)d_in[0];
    const float* cb = (const float*)d_in[1];
    // Defensive: metadata order should be (x, codebooks); swap if sizes say otherwise.
    if (n_in >= 2 && in_sizes[0] == QL * KCODES * CD &&
        in_sizes[1] == NBATCH * CD * TT) {
        const float* tmp = x; x = cb; cb = tmp;
    }
    float* out = (float*)d_out;

    cudaFuncSetAttribute(vq_main_kernel,
                         cudaFuncAttributeMaxDynamicSharedMemorySize, SMEM_BYTES);

    zero_hist_kernel<<<6, 1024>>>();
    cbnorm_kernel<<<(QL * KCODES * 32 + 255) / 256, 256>>>(cb);
    vq_main_kernel<<<NBLK, 256, SMEM_BYTES>>>(x, cb, out);
    finalize_kernel<<<1, 512>>>(out, out_size);
}

// round 5
// speedup vs baseline: 1.6092x; 1.6092x over previous
#include <cuda_runtime.h>
#include <math.h>

// ResidualVQ fused single-kernel for B200 (sm_100a).
// x: (32, 512, 1024) fp32, codebooks: (6, 1024, 512) fp32.
// out = x - residual_final, + loss & perplexity scalars appended.
//
// Pass 1: f32x2 FFMA GEMM (code-pair packed accumulators) nominates top-2
// codes per token with approximate distances (approx ||cb||^2, err ~2e-4).
// Decision: if top-2 gap < MARGIN, rescore both candidates with bit-replicas
// of the reference pipeline (serial-k FFMA dot, XLA lane-strided row norms,
// fp32 rounding grid, first-index tie-break).
// Residual update replicates the reference STE rounding exactly.
// Single launch: histogram + finalize handled by last-CTA drain; all global
// state (hist, counter) is restored before kernel exit => replay-safe.

#define QL      6
#define KCODES  1024
#define CD      512
#define TT      1024
#define NBATCH  32
#define NTOK    (NBATCH * TT)       // 32768
#define TILE_T  64
#define NBLK    (NTOK / TILE_T)     // 512
#define KC      64                  // c-phase width
#define NPH     (CD / KC)           // 8
#define CCHUNK  128                 // codes per chunk
#define NCH     (KCODES / CCHUNK)   // 8
#define BST     130                 // words per kk row (128 codes + pad, even)
#define BUFW    (KC * BST)          // 8320 words per buffer
#define OUT_ELEMS (NBATCH * CD * TT)
#define MARGIN  0.03f

// smem word offsets
#define OFF_AS   0
#define OFF_BS   (CD * TILE_T)               // 32768
#define OFF_CN   (OFF_BS + 2 * BUFW)         // +16640 = 49408
#define OFF_IDX  (OFF_CN + CCHUNK)           // 49536
#define OFF_RN   (OFF_IDX + TILE_T)          // 49600
#define OFF_RED  (OFF_RN + TILE_T)           // 49664
#define OFF_FLAG (OFF_RED + 8)               // 49672
#define SMEM_WORDS (OFF_FLAG + 2)
#define SMEM_BYTES (SMEM_WORDS * 4)          // ~198.7 KB

__device__ int   g_hist[QL * KCODES];        // zero at load; re-zeroed each call
__device__ float g_losspart[QL * NBLK];
__device__ int   g_done;                     // zero at load; reset each call

union U2 { unsigned long long u; float2 f; };

__device__ __forceinline__ void ffma2(unsigned long long& d,
                                      unsigned long long a,
                                      unsigned long long b) {
    asm("fma.rn.f32x2 %0, %1, %2, %0;" : "+l"(d) : "l"(a), "l"(b));
}

__device__ __forceinline__ unsigned long long pack2(float a) {
    unsigned long long d;
    asm("mov.b64 %0, {%1, %1};" : "=l"(d) : "r"(__float_as_uint(a)));
    return d;
}

// XLA-replica row norm of one token's residual column in As (fp32 rn).
__device__ __forceinline__ float xla_rownorm_tok(const float* __restrict__ As,
                                                 int tok) {
    float p[32];
    #pragma unroll
    for (int l = 0; l < 32; l++) {
        float a = 0.f;
        #pragma unroll
        for (int i = 0; i < 16; i++) {
            float r = As[(l + 32 * i) * TILE_T + tok];
            a = __fadd_rn(a, __fmul_rn(r, r));
        }
        p[l] = a;
    }
    #pragma unroll
    for (int o = 16; o; o >>= 1)
        #pragma unroll
        for (int l = 0; l < o; l++) p[l] = __fadd_rn(p[l], p[l + o]);
    return p[0];
}

// XLA-replica row norm of a gmem codebook row (rescore path only).
__device__ float xla_rownorm_row(const float* __restrict__ row) {
    float p[32];
    #pragma unroll
    for (int l = 0; l < 32; l++) {
        float a = 0.f;
        #pragma unroll
        for (int i = 0; i < 16; i++) {
            float v = row[l + 32 * i];
            a = __fadd_rn(a, __fmul_rn(v, v));
        }
        p[l] = a;
    }
    #pragma unroll
    for (int o = 16; o; o >>= 1)
        #pragma unroll
        for (int l = 0; l < o; l++) p[l] = __fadd_rn(p[l], p[l + o]);
    return p[0];
}

__device__ __forceinline__ void top2_insert(float v, int code,
                                            float& v1, int& i1,
                                            float& v2, int& i2) {
    if (v < v1) { v2 = v1; i2 = i1; v1 = v; i1 = code; }
    else if (v < v2) { v2 = v; i2 = code; }
}

__device__ float block_reduce_256(float v, float* sh) {
    int t = threadIdx.x;
    #pragma unroll
    for (int o = 16; o; o >>= 1) v += __shfl_down_sync(0xffffffffu, v, o);
    if ((t & 31) == 0) sh[t >> 5] = v;
    __syncthreads();
    float r = 0.f;
    if (t < 8) {
        r = sh[t];
        #pragma unroll
        for (int o = 4; o; o >>= 1) r += __shfl_down_sync(0x000000ffu, r, o, 8);
    }
    __syncthreads();
    return r;   // valid on thread 0
}

// Thread map (256 threads): g = tx>>4 (tokens 4g..4g+3), col = tx&15
// (code pairs cp = col+16p, p=0..3 -> codes 2cp, 2cp+1 within the chunk).
__global__ __launch_bounds__(256, 1)
void vq_main_kernel(const float* __restrict__ x, const float* __restrict__ cb,
                    float* __restrict__ out, int out_size) {
    extern __shared__ float smem[];
    float* As   = smem + OFF_AS;        // [512][64] residual
    float* Bs   = smem + OFF_BS;        // 2 x [64 kk][130] staged B
    float* cn_s = smem + OFF_CN;        // [128] approx code norms (per chunk)
    int*   idxs = (int*)(smem + OFF_IDX);
    float* Rn_s = smem + OFF_RN;        // [64] XLA-replica ||r||^2
    float* red  = smem + OFF_RED;
    int*   flag = (int*)(smem + OFF_FLAG);

    const int tx  = threadIdx.x;
    const int blk = blockIdx.x;
    const int n   = blk >> 4;
    const int t0  = (blk & 15) << 6;
    const float* xblk = x + (size_t)n * CD * TT + t0;

    // Load x tile transposed into As[c][tok]; coalesced over tok.
    {
        const int tok = tx & 63, c0 = tx >> 6;
        for (int k = 0; k < CD / 4; k++) {
            int c = c0 + k * 4;
            As[c * TILE_T + tok] = xblk[c * TT + tok];
        }
    }
    __syncthreads();

    const int g    = tx >> 4;
    const int col  = tx & 15;
    const int ccl  = col * 4;
    const int tokm = tx >> 2, q4 = tx & 3;

    if (tx < TILE_T) Rn_s[tx] = xla_rownorm_tok(As, tx);
    __syncthreads();

    for (int q = 0; q < QL; q++) {
        const float* cbq = cb + (size_t)q * KCODES * CD;
        float minv[4]  = {3.4e38f, 3.4e38f, 3.4e38f, 3.4e38f};
        float min2v[4] = {3.4e38f, 3.4e38f, 3.4e38f, 3.4e38f};
        int   mini[4]  = {0, 0, 0, 0};
        int   min2i[4] = {1, 1, 1, 1};
        const float Rn0 = Rn_s[4*g+0], Rn1 = Rn_s[4*g+1];
        const float Rn2 = Rn_s[4*g+2], Rn3 = Rn_s[4*g+3];

        for (int ch = 0; ch < NCH; ch++) {
            const int k0 = ch * CCHUNK;
            U2 acc[4][4];
            #pragma unroll
            for (int t = 0; t < 4; t++)
                #pragma unroll
                for (int p = 0; p < 4; p++) acc[t][p].u = 0ull;
            float hr[8];
            #pragma unroll
            for (int r = 0; r < 8; r++) hr[r] = 0.f;

            // Prologue: load + stage phase 0 (codes k0+g+16r, c = ccl..ccl+3).
            float4 pf[8];
            #pragma unroll
            for (int r = 0; r < 8; r++)
                pf[r] = *(const float4*)&cbq[(size_t)(k0 + g + 16 * r) * CD + ccl];
            #pragma unroll
            for (int r = 0; r < 8; r++) {
                float* dst = Bs + 0 * BUFW;   // buf0
                dst[(ccl + 0) * BST + g + 16 * r] = pf[r].x;
                dst[(ccl + 1) * BST + g + 16 * r] = pf[r].y;
                dst[(ccl + 2) * BST + g + 16 * r] = pf[r].z;
                dst[(ccl + 3) * BST + g + 16 * r] = pf[r].w;
                hr[r] += pf[r].x*pf[r].x + pf[r].y*pf[r].y
                       + pf[r].z*pf[r].z + pf[r].w*pf[r].w;
            }
            __syncthreads();

            for (int ph = 0; ph < NPH; ph++) {
                const float* Bc = Bs + (ph & 1) * BUFW;
                // Prefetch next phase (issues LDGs early; hidden by compute).
                if (ph < NPH - 1) {
                    #pragma unroll
                    for (int r = 0; r < 8; r++)
                        pf[r] = *(const float4*)&cbq[(size_t)(k0 + g + 16 * r) * CD +
                                                     (ph + 1) * KC + ccl];
                }
                // Compute 64 kk steps.
                const float* Ap = As + ph * KC * TILE_T + 4 * g;
                #pragma unroll 8
                for (int kk = 0; kk < KC; kk++) {
                    float4 a4 = *(const float4*)(Ap + kk * TILE_T);
                    unsigned long long A0 = pack2(a4.x), A1 = pack2(a4.y);
                    unsigned long long A2 = pack2(a4.z), A3 = pack2(a4.w);
                    #pragma unroll
                    for (int p = 0; p < 4; p++) {
                        unsigned long long bv = *(const unsigned long long*)
                            (Bc + kk * BST + 2 * (col + 16 * p));
                        ffma2(acc[0][p].u, A0, bv);
                        ffma2(acc[1][p].u, A1, bv);
                        ffma2(acc[2][p].u, A2, bv);
                        ffma2(acc[3][p].u, A3, bv);
                    }
                }
                // Stage next phase into the other buffer (overlaps compute tail).
                if (ph < NPH - 1) {
                    float* dst = Bs + ((ph + 1) & 1) * BUFW;
                    #pragma unroll
                    for (int r = 0; r < 8; r++) {
                        dst[(ccl + 0) * BST + g + 16 * r] = pf[r].x;
                        dst[(ccl + 1) * BST + g + 16 * r] = pf[r].y;
                        dst[(ccl + 2) * BST + g + 16 * r] = pf[r].z;
                        dst[(ccl + 3) * BST + g + 16 * r] = pf[r].w;
                        hr[r] += pf[r].x*pf[r].x + pf[r].y*pf[r].y
                               + pf[r].z*pf[r].z + pf[r].w*pf[r].w;
                    }
                } else {
                    // Reduce approx code norms over the 16 c-columns.
                    #pragma unroll
                    for (int r = 0; r < 8; r++) {
                        float s = hr[r];
                        #pragma unroll
                        for (int o = 8; o; o >>= 1)
                            s += __shfl_down_sync(0xffffffffu, s, o, 16);
                        if (col == 0) cn_s[g + 16 * r] = s;
                    }
                }
                __syncthreads();
            }

            // Chunk epilogue: approx dist = (Rn - 2*dot) + cn ; running top-2.
            #pragma unroll
            for (int p = 0; p < 4; p++) {
                const int cp = col + 16 * p;
                const int ca = k0 + 2 * cp, cbi = ca + 1;
                const float cna = cn_s[2 * cp], cnb = cn_s[2 * cp + 1];
                float v;
                v = (Rn0 - 2.f * acc[0][p].f.x) + cna;
                top2_insert(v, ca,  minv[0], mini[0], min2v[0], min2i[0]);
                v = (Rn0 - 2.f * acc[0][p].f.y) + cnb;
                top2_insert(v, cbi, minv[0], mini[0], min2v[0], min2i[0]);
                v = (Rn1 - 2.f * acc[1][p].f.x) + cna;
                top2_insert(v, ca,  minv[1], mini[1], min2v[1], min2i[1]);
                v = (Rn1 - 2.f * acc[1][p].f.y) + cnb;
                top2_insert(v, cbi, minv[1], mini[1], min2v[1], min2i[1]);
                v = (Rn2 - 2.f * acc[2][p].f.x) + cna;
                top2_insert(v, ca,  minv[2], mini[2], min2v[2], min2i[2]);
                v = (Rn2 - 2.f * acc[2][p].f.y) + cnb;
                top2_insert(v, cbi, minv[2], mini[2], min2v[2], min2i[2]);
                v = (Rn3 - 2.f * acc[3][p].f.x) + cna;
                top2_insert(v, ca,  minv[3], mini[3], min2v[3], min2i[3]);
                v = (Rn3 - 2.f * acc[3][p].f.y) + cnb;
                top2_insert(v, cbi, minv[3], mini[3], min2v[3], min2i[3]);
            }
            __syncthreads();   // cn_s reused next chunk
        }

        // Cross-thread top-2 merge over the 16 code columns (lex: lower idx).
        #pragma unroll
        for (int i = 0; i < 4; i++) {
            float v1 = minv[i], v2 = min2v[i];
            int   i1 = mini[i], i2 = min2i[i];
            #pragma unroll
            for (int o = 8; o; o >>= 1) {
                float w1 = __shfl_down_sync(0xffffffffu, v1, o, 16);
                int   j1 = __shfl_down_sync(0xffffffffu, i1, o, 16);
                float w2 = __shfl_down_sync(0xffffffffu, v2, o, 16);
                int   j2 = __shfl_down_sync(0xffffffffu, i2, o, 16);
                if (w1 < v1 || (w1 == v1 && j1 < i1)) {
                    v2 = v1; i2 = i1;
                    if (w2 < v2 || (w2 == v2 && j2 < i2)) { v2 = w2; i2 = j2; }
                    v1 = w1; i1 = j1;
                } else {
                    if (w1 < v2 || (w1 == v2 && j1 < i2)) { v2 = w1; i2 = j1; }
                }
            }
            if (col == 0) {
                int id = i1;
                if (v2 - v1 < MARGIN) {
                    // Reference-replica rescore of the two candidates.
                    const int tok = 4 * g + i;
                    const float Rn = Rn_s[tok];
                    const float* ra = cbq + (size_t)i1 * CD;
                    const float* rb = cbq + (size_t)i2 * CD;
                    float ma = 0.f, mb = 0.f;
                    #pragma unroll 8
                    for (int c = 0; c < CD; c++) {
                        float r = As[c * TILE_T + tok];
                        ma = __fmaf_rn(r, ra[c], ma);
                        mb = __fmaf_rn(r, rb[c], mb);
                    }
                    float cna = xla_rownorm_row(ra);
                    float cnb = xla_rownorm_row(rb);
                    float va = __fadd_rn(__fsub_rn(Rn, __fmul_rn(2.f, ma)), cna);
                    float vb = __fadd_rn(__fsub_rn(Rn, __fmul_rn(2.f, mb)), cnb);
                    if (vb < va || (vb == va && i2 < i1)) id = i2;
                }
                idxs[4 * g + i] = id;
                atomicAdd(&g_hist[q * KCODES + id], 1);
            }
        }
        __syncthreads();

        // Residual update with the reference STE rounding:
        // t = fl(xd - r); quant = fl(r + t); r_new = fl(r - quant)
        {
            const float* row = cbq + (size_t)idxs[tokm] * CD;
            for (int k = 0; k < CD / 16; k++) {
                const int c = k * 16 + q4 * 4;
                float4 w = *(const float4*)&row[c];
                #pragma unroll
                for (int e = 0; e < 4; e++) {
                    float xd = (&w.x)[e];
                    float* p = &As[(c + e) * TILE_T + tokm];
                    float r = *p;
                    float t = __fsub_rn(xd, r);
                    float quant = __fadd_rn(r, t);
                    *p = __fsub_rn(r, quant);
                }
            }
        }
        __syncthreads();

        // New XLA-replica ||r||^2 (feeds next layer + loss).
        if (tx < TILE_T) Rn_s[tx] = xla_rownorm_tok(As, tx);
        __syncthreads();

        if (tx < 32) {
            float s = Rn_s[tx] + Rn_s[tx + 32];
            #pragma unroll
            for (int o = 16; o; o >>= 1) s += __shfl_down_sync(0xffffffffu, s, o);
            if (tx == 0) g_losspart[q * NBLK + blk] = s;
        }
        __syncthreads();
    }

    // out = x - residual_final, transposed back; coalesced over tok.
    {
        const int tok = tx & 63, c0 = tx >> 6;
        float* oblk = out + (size_t)n * CD * TT + t0;
        for (int k = 0; k < CD / 4; k++) {
            int c = c0 + k * 4;
            oblk[c * TT + tok] = xblk[c * TT + tok] - As[c * TILE_T + tok];
        }
    }

    // ---- Last-CTA drain: loss + perplexity, then restore global state. ----
    __syncthreads();
    if (tx == 0) {
        __threadfence();
        flag[0] = (atomicAdd(&g_done, 1) == NBLK - 1) ? 1 : 0;
    }
    __syncthreads();
    if (flag[0]) {
        __threadfence();
        float ls = 0.f;
        for (int i = tx; i < QL * NBLK; i += 256) ls += g_losspart[i];
        ls = block_reduce_256(ls, red);
        float lossval = ls / ((float)NTOK * (float)CD * (float)QL);

        float ptot = 0.f;
        for (int q = 0; q < QL; q++) {
            float s = 0.f;
            for (int k = tx; k < KCODES; k += 256) {
                float p = (float)g_hist[q * KCODES + k] * (1.0f / 32768.0f);
                s += p * logf(p + 1e-7f);
            }
            s = block_reduce_256(s, red);
            if (tx == 0) ptot += expf(-s);
        }
        if (tx == 0) {
            if (out_size >= OUT_ELEMS + 2) {
                out[OUT_ELEMS]     = lossval;
                out[OUT_ELEMS + 1] = ptot / (float)QL;
            } else if (out_size == OUT_ELEMS + 1) {
                out[OUT_ELEMS] = lossval;
            }
        }
        // Restore state for the next (graph-replayed) call.
        for (int i = tx; i < QL * KCODES; i += 256) g_hist[i] = 0;
        if (tx == 0) { g_done = 0; __threadfence(); }
    }
}

extern "C" void kernel_launch(void* const* d_in, const int* in_sizes, int n_in,
                              void* d_out, int out_size) {
    const float* x  = (const float*)d_in[0];
    const float* cb = (const float*)d_in[1];
    if (n_in >= 2 && in_sizes[0] == QL * KCODES * CD &&
        in_sizes[1] == NBATCH * CD * TT) {
        const float* tmp = x; x = cb; cb = tmp;
    }
    float* out = (float*)d_out;

    cudaFuncSetAttribute(vq_main_kernel,
                         cudaFuncAttributeMaxDynamicSharedMemorySize, SMEM_BYTES);
    vq_main_kernel<<<NBLK, 256, SMEM_BYTES>>>(x, cb, out, out_size);
}

// round 8
// speedup vs baseline: 2.1184x; 1.3164x over previous
#include <cuda_runtime.h>
#include <math.h>
#include <stdint.h>

// ResidualVQ on B200 (sm_100 base target) — legacy tensor-core tf32
// mma.sync distance GEMM + exact reference-replica argmin rescue.
//
// x: (32, 512, 1024) fp32, codebooks: (6, 1024, 512) fp32.
// out = x - residual_final, + loss & perplexity scalars appended.

#define QL      6
#define KCODES  1024
#define CD      512
#define TT      1024
#define NBATCH  32
#define NTOK    (NBATCH * TT)        // 32768
#define TILE_T  64
#define NBLK    (NTOK / TILE_T)      // 512
#define NPASS   2                    // code passes per layer (512 codes each)
#define PCODES  512
#define KP      8                    // c per phase (one mma k-tile)
#define NPH     (CD / KP)            // 64 phases per pass
#define BST     12                   // staged-B words per code (8 + pad)
#define RST     520                  // Rs words per token (512 + pad)
#define OUT_ELEMS (NBATCH * CD * TT)
#define MARGIN  0.25f
#define NSLOT   16                   // 2 passes x 8 warps
#define FINF    3.4e38f

// ---- smem word offsets ----
#define W_RS    0
#define W_B     (TILE_T * RST)                  // 33280
#define W_CN    (W_B + 2 * PCODES * BST)        // 45568
#define W_CV    (W_CN + KCODES)                 // 46592
#define W_CI    (W_CV + TILE_T * NSLOT * 3)     // 49664
#define W_RN    (W_CI + TILE_T * NSLOT * 3)     // 52736
#define W_IDX   (W_RN + TILE_T)
#define W_RED   (W_IDX + TILE_T)
#define W_FLAG  (W_RED + 8)
#define SMEM_WORDS (W_FLAG + 2)
#define SMEM_BYTES (SMEM_WORDS * 4)             // ~211.5 KB

__device__ float g_cbnorm[QL * KCODES];
__device__ int   g_hist[QL * KCODES];
__device__ float g_losspart[QL * NBLK];
__device__ int   g_done;

// ---------------- tensor-core helpers (sm_80+ base ISA) ----------------
__device__ __forceinline__ uint32_t f2tf(float f) {
    uint32_t r; asm("cvt.rna.tf32.f32 %0, %1;" : "=r"(r) : "f"(f)); return r;
}
__device__ __forceinline__ void mma8(float* d, uint32_t a0, uint32_t a1,
                                     uint32_t a2, uint32_t a3,
                                     uint32_t b0, uint32_t b1) {
    asm volatile(
        "mma.sync.aligned.m16n8k8.row.col.f32.tf32.tf32.f32 "
        "{%0,%1,%2,%3}, {%4,%5,%6,%7}, {%8,%9}, {%0,%1,%2,%3};"
        : "+f"(d[0]), "+f"(d[1]), "+f"(d[2]), "+f"(d[3])
        : "r"(a0), "r"(a1), "r"(a2), "r"(a3), "r"(b0), "r"(b1));
}

// ---------------- replica arithmetic (bit-matches reference) ----------------
__global__ void cbnorm_kernel(const float* __restrict__ cb) {
    int w    = (blockIdx.x * blockDim.x + threadIdx.x) >> 5;
    int lane = threadIdx.x & 31;
    if (w >= QL * KCODES) return;
    const float* row = cb + (size_t)w * CD;
    float a = 0.f;
    #pragma unroll
    for (int i = 0; i < CD / 32; i++) {
        float v = row[lane + 32 * i];
        a = __fadd_rn(a, __fmul_rn(v, v));
    }
    #pragma unroll
    for (int o = 16; o; o >>= 1)
        a = __fadd_rn(a, __shfl_down_sync(0xffffffffu, a, o));
    if (lane == 0) g_cbnorm[w] = a;
}

// Exact replica distance: serial ascending-k FFMA dot + fp32 rounding grid.
__device__ float replica_dist(const float* __restrict__ rtok,
                              const float* __restrict__ crow,
                              float Rn, float cn) {
    float m = 0.f;
    for (int c = 0; c < CD; c += 4) {
        float4 b = *(const float4*)&crow[c];
        m = __fmaf_rn(rtok[c + 0], b.x, m);
        m = __fmaf_rn(rtok[c + 1], b.y, m);
        m = __fmaf_rn(rtok[c + 2], b.z, m);
        m = __fmaf_rn(rtok[c + 3], b.w, m);
    }
    return __fadd_rn(__fsub_rn(Rn, __fmul_rn(2.f, m)), cn);
}

__device__ float block_reduce_256(float v, float* sh) {
    int t = threadIdx.x;
    #pragma unroll
    for (int o = 16; o; o >>= 1) v += __shfl_down_sync(0xffffffffu, v, o);
    if ((t & 31) == 0) sh[t >> 5] = v;
    __syncthreads();
    float r = 0.f;
    if (t < 8) {
        r = sh[t];
        #pragma unroll
        for (int o = 4; o; o >>= 1) r += __shfl_down_sync(0x000000ffu, r, o, 8);
    }
    __syncthreads();
    return r;
}

// Merge this lane's sorted lex triple with lane^off's triple.
__device__ __forceinline__ void lexmerge3(float* v, int* idx, int off) {
    float wv0 = __shfl_xor_sync(0xffffffffu, v[0], off);
    float wv1 = __shfl_xor_sync(0xffffffffu, v[1], off);
    float wv2 = __shfl_xor_sync(0xffffffffu, v[2], off);
    int   wi0 = __shfl_xor_sync(0xffffffffu, idx[0], off);
    int   wi1 = __shfl_xor_sync(0xffffffffu, idx[1], off);
    int   wi2 = __shfl_xor_sync(0xffffffffu, idx[2], off);
    float av[3] = {v[0], v[1], v[2]};
    int   ai[3] = {idx[0], idx[1], idx[2]};
    float bv[3] = {wv0, wv1, wv2};
    int   bi[3] = {wi0, wi1, wi2};
    int a = 0, b = 0;
    #pragma unroll
    for (int o = 0; o < 3; o++) {
        bool tA = (b >= 3) || (a < 3 && (av[a] < bv[b] ||
                   (av[a] == bv[b] && ai[a] <= bi[b])));
        if (tA) { v[o] = av[a]; idx[o] = ai[a]; a++; }
        else    { v[o] = bv[b]; idx[o] = bi[b]; b++; }
    }
}

__device__ __forceinline__ void top2_ins(float nv, int nc, float* v, int* idx) {
    if (nv < v[0] || (nv == v[0] && nc < idx[0])) {
        v[1] = v[0]; idx[1] = idx[0]; v[0] = nv; idx[0] = nc;
    } else if (nv < v[1] || (nv == v[1] && nc < idx[1])) {
        v[1] = nv; idx[1] = nc;
    }
}

// ---------------- main kernel ----------------
__global__ __launch_bounds__(256, 1)
void vq_main_kernel(const float* __restrict__ x, const float* __restrict__ cb,
                    float* __restrict__ out, int out_size) {
    extern __shared__ float smem[];
    float*    Rs   = smem + W_RS;                 // [64][520] residual
    uint32_t* Bst  = (uint32_t*)(smem + W_B);     // 2 x [512][12] tf32 bits
    float*    cn_s = smem + W_CN;                 // [1024] replica code norms
    float*    cd_v = smem + W_CV;                 // [64][16][3] cand values
    int*      cd_i = (int*)(smem + W_CI);
    float*    Rn_s = smem + W_RN;                 // [64] replica ||r||^2
    int*      idxs = (int*)(smem + W_IDX);
    float*    red  = smem + W_RED;
    int*      flag = (int*)(smem + W_FLAG);

    const int tx   = threadIdx.x;
    const int wid  = tx >> 5;
    const int lane = tx & 31;
    const int lg   = lane >> 2;    // 0..7
    const int la   = lane & 3;     // 0..3
    const int blk  = blockIdx.x;
    const int n    = blk >> 4;
    const int t0   = (blk & 15) << 6;
    const float* xblk = x + (size_t)n * CD * TT + t0;

    // ---- transpose x into Rs[tok][c] ----
    for (int it = 0; it < 32; it++) {
        int c = (tx >> 4) + 16 * it;
        int t4 = (tx & 15) * 4;
        float4 v = *(const float4*)&xblk[(size_t)c * TT + t4];
        Rs[(t4 + 0) * RST + c] = v.x;
        Rs[(t4 + 1) * RST + c] = v.y;
        Rs[(t4 + 2) * RST + c] = v.z;
        Rs[(t4 + 3) * RST + c] = v.w;
    }
    __syncthreads();

    // ---- initial replica Rn (XLA warp-reduce pattern) ----
    for (int t = 0; t < 8; t++) {
        int tok = wid * 8 + t;
        const float* rr = Rs + tok * RST;
        float a = 0.f;
        #pragma unroll
        for (int i = 0; i < 16; i++) {
            float r = rr[lane + 32 * i];
            a = __fadd_rn(a, __fmul_rn(r, r));
        }
        #pragma unroll
        for (int o = 16; o; o >>= 1)
            a = __fadd_rn(a, __shfl_down_sync(0xffffffffu, a, o));
        if (lane == 0) Rn_s[tok] = a;
    }
    __syncthreads();

    for (int q = 0; q < QL; q++) {
        const float* cbq = cb + (size_t)q * KCODES * CD;
        for (int i = tx; i < KCODES; i += 256) cn_s[i] = g_cbnorm[q * KCODES + i];
        __syncthreads();

        for (int pass = 0; pass < NPASS; pass++) {
            float ac[4][8][4];
            #pragma unroll
            for (int mt = 0; mt < 4; mt++)
                #pragma unroll
                for (int nt = 0; nt < 8; nt++)
                    #pragma unroll
                    for (int e = 0; e < 4; e++) ac[mt][nt][e] = 0.f;

            // stage phase 0 directly
            {
                uint32_t* dst = Bst;
                #pragma unroll
                for (int h = 0; h < 2; h++) {
                    int code = tx + 256 * h;
                    const float* s = cbq + (size_t)(pass * PCODES + code) * CD;
                    float4 v0 = *(const float4*)s;
                    float4 v1 = *(const float4*)(s + 4);
                    uint4 u0 = make_uint4(f2tf(v0.x), f2tf(v0.y), f2tf(v0.z), f2tf(v0.w));
                    uint4 u1 = make_uint4(f2tf(v1.x), f2tf(v1.y), f2tf(v1.z), f2tf(v1.w));
                    *(uint4*)&dst[code * BST] = u0;
                    *(uint4*)&dst[code * BST + 4] = u1;
                }
            }
            __syncthreads();

            for (int p = 0; p < NPH; p++) {
                float4 pre0, pre1, pre2, pre3;
                if (p + 1 < NPH) {
                    const float* s0 = cbq + (size_t)(pass * PCODES + tx) * CD + (p + 1) * KP;
                    const float* s1 = cbq + (size_t)(pass * PCODES + tx + 256) * CD + (p + 1) * KP;
                    pre0 = *(const float4*)s0; pre1 = *(const float4*)(s0 + 4);
                    pre2 = *(const float4*)s1; pre3 = *(const float4*)(s1 + 4);
                }
                const uint32_t* Bb = Bst + (p & 1) * PCODES * BST;
                uint32_t b0[8], b1[8];
                #pragma unroll
                for (int nt = 0; nt < 8; nt++) {
                    uint2 bb = *(const uint2*)&Bb[(wid * 64 + nt * 8 + lg) * BST + 2 * la];
                    b0[nt] = bb.x; b1[nt] = bb.y;
                }
                const int cb0 = p * KP + 2 * la;
                #pragma unroll
                for (int mt = 0; mt < 4; mt++) {
                    int ta = 16 * mt + lg;
                    float2 lo = *(const float2*)&Rs[ta * RST + cb0];
                    float2 hi = *(const float2*)&Rs[(ta + 8) * RST + cb0];
                    uint32_t a0 = f2tf(lo.x), a2 = f2tf(lo.y);
                    uint32_t a1 = f2tf(hi.x), a3 = f2tf(hi.y);
                    #pragma unroll
                    for (int nt = 0; nt < 8; nt++)
                        mma8(ac[mt][nt], a0, a1, a2, a3, b0[nt], b1[nt]);
                }
                if (p + 1 < NPH) {
                    uint32_t* dst = Bst + ((p + 1) & 1) * PCODES * BST;
                    uint4 u0 = make_uint4(f2tf(pre0.x), f2tf(pre0.y), f2tf(pre0.z), f2tf(pre0.w));
                    uint4 u1 = make_uint4(f2tf(pre1.x), f2tf(pre1.y), f2tf(pre1.z), f2tf(pre1.w));
                    uint4 u2 = make_uint4(f2tf(pre2.x), f2tf(pre2.y), f2tf(pre2.z), f2tf(pre2.w));
                    uint4 u3 = make_uint4(f2tf(pre3.x), f2tf(pre3.y), f2tf(pre3.z), f2tf(pre3.w));
                    *(uint4*)&dst[tx * BST] = u0;
                    *(uint4*)&dst[tx * BST + 4] = u1;
                    *(uint4*)&dst[(tx + 256) * BST] = u2;
                    *(uint4*)&dst[(tx + 256) * BST + 4] = u3;
                }
                __syncthreads();
            }

            // ---- epilogue: dist = (Rn - 2*dot) + cn ; per-warp top-3 ----
            const int slot = pass * 8 + wid;
            #pragma unroll
            for (int mt = 0; mt < 4; mt++) {
                int tA = 16 * mt + lg, tB = tA + 8;
                float RnA = Rn_s[tA], RnB = Rn_s[tB];
                float vA[3] = {FINF, FINF, FINF}; int iA[3] = {0, 1, 2};
                float vB[3] = {FINF, FINF, FINF}; int iB[3] = {0, 1, 2};
                #pragma unroll
                for (int nt = 0; nt < 8; nt++) {
                    int c0 = pass * PCODES + wid * 64 + nt * 8 + 2 * la;
                    float cn0 = cn_s[c0], cn1 = cn_s[c0 + 1];
                    top2_ins((RnA - 2.f * ac[mt][nt][0]) + cn0, c0,     vA, iA);
                    top2_ins((RnA - 2.f * ac[mt][nt][1]) + cn1, c0 + 1, vA, iA);
                    top2_ins((RnB - 2.f * ac[mt][nt][2]) + cn0, c0,     vB, iB);
                    top2_ins((RnB - 2.f * ac[mt][nt][3]) + cn1, c0 + 1, vB, iB);
                }
                lexmerge3(vA, iA, 1); lexmerge3(vA, iA, 2);
                lexmerge3(vB, iB, 1); lexmerge3(vB, iB, 2);
                if (la == 0) {
                    #pragma unroll
                    for (int j = 0; j < 3; j++) {
                        cd_v[(tA * NSLOT + slot) * 3 + j] = vA[j];
                        cd_i[(tA * NSLOT + slot) * 3 + j] = iA[j];
                        cd_v[(tB * NSLOT + slot) * 3 + j] = vB[j];
                        cd_i[(tB * NSLOT + slot) * 3 + j] = iB[j];
                    }
                }
            }
            __syncthreads();
        }

        // ---- decision: global lex-min; margin -> exact replica rescore ----
        if (tx < TILE_T) {
            const int tok = tx;
            const float* cvp = cd_v + tok * NSLOT * 3;
            const int*   cip = cd_i + tok * NSLOT * 3;
            float v1 = FINF, v2 = FINF; int i1 = 0x7fffffff;
            for (int j = 0; j < NSLOT * 3; j++) {
                float v = cvp[j]; int c = cip[j];
                if (v < v1 || (v == v1 && c < i1)) { v2 = v1; v1 = v; i1 = c; }
                else if (v < v2) { v2 = v; }
            }
            int id = i1;
            if (v2 - v1 < MARGIN) {
                const float Rn = Rn_s[tok];
                const float* rtok = Rs + tok * RST;
                float bv = FINF; int bi = 0x7fffffff;
                float lim = v1 + MARGIN;
                for (int j = 0; j < NSLOT * 3; j++) {
                    if (cvp[j] <= lim) {
                        int c = cip[j];
                        float d = replica_dist(rtok, cbq + (size_t)c * CD, Rn, cn_s[c]);
                        if (d < bv || (d == bv && c < bi)) { bv = d; bi = c; }
                    }
                }
                id = bi;
            }
            idxs[tok] = id;
            atomicAdd(&g_hist[q * KCODES + id], 1);
        }
        __syncthreads();

        // ---- STE-replica residual update + new replica Rn ----
        for (int t = 0; t < 8; t++) {
            int tok = wid * 8 + t;
            const float* row = cbq + (size_t)idxs[tok] * CD;
            float* rr = Rs + tok * RST;
            float a = 0.f;
            #pragma unroll
            for (int i = 0; i < 16; i++) {
                int c = lane + 32 * i;
                float r  = rr[c];
                float xd = row[c];
                float tt = __fsub_rn(xd, r);
                float qv = __fadd_rn(r, tt);
                float rn = __fsub_rn(r, qv);
                rr[c] = rn;
                a = __fadd_rn(a, __fmul_rn(rn, rn));
            }
            #pragma unroll
            for (int o = 16; o; o >>= 1)
                a = __fadd_rn(a, __shfl_down_sync(0xffffffffu, a, o));
            if (lane == 0) Rn_s[tok] = a;
        }
        __syncthreads();
        if (tx < 32) {
            float s = Rn_s[tx] + Rn_s[tx + 32];
            #pragma unroll
            for (int o = 16; o; o >>= 1) s += __shfl_down_sync(0xffffffffu, s, o);
            if (tx == 0) g_losspart[q * NBLK + blk] = s;
        }
        __syncthreads();
    }

    // ---- out = x - residual_final (transpose back) ----
    {
        float* oblk = out + (size_t)n * CD * TT + t0;
        for (int it = 0; it < 32; it++) {
            int c = (tx >> 4) + 16 * it;
            int t4 = (tx & 15) * 4;
            float4 xv = *(const float4*)&xblk[(size_t)c * TT + t4];
            float4 ov;
            ov.x = xv.x - Rs[(t4 + 0) * RST + c];
            ov.y = xv.y - Rs[(t4 + 1) * RST + c];
            ov.z = xv.z - Rs[(t4 + 2) * RST + c];
            ov.w = xv.w - Rs[(t4 + 3) * RST + c];
            *(float4*)&oblk[(size_t)c * TT + t4] = ov;
        }
    }

    // ---- last-CTA drain: loss + perplexity, restore global state ----
    __syncthreads();
    if (tx == 0) {
        __threadfence();
        flag[0] = (atomicAdd(&g_done, 1) == NBLK - 1) ? 1 : 0;
    }
    __syncthreads();
    if (flag[0]) {
        __threadfence();
        float ls = 0.f;
        for (int i = tx; i < QL * NBLK; i += 256) ls += g_losspart[i];
        ls = block_reduce_256(ls, red);
        float lossval = ls / ((float)NTOK * (float)CD * (float)QL);

        float ptot = 0.f;
        for (int qq = 0; qq < QL; qq++) {
            float s = 0.f;
            for (int k = tx; k < KCODES; k += 256) {
                float p = (float)g_hist[qq * KCODES + k] * (1.0f / 32768.0f);
                s += p * logf(p + 1e-7f);
            }
            s = block_reduce_256(s, red);
            if (tx == 0) ptot += expf(-s);
        }
        if (tx == 0) {
            if (out_size >= OUT_ELEMS + 2) {
                out[OUT_ELEMS]     = lossval;
                out[OUT_ELEMS + 1] = ptot / (float)QL;
            } else if (out_size == OUT_ELEMS + 1) {
                out[OUT_ELEMS] = lossval;
            }
        }
        for (int i = tx; i < QL * KCODES; i += 256) g_hist[i] = 0;
        if (tx == 0) { g_done = 0; __threadfence(); }
    }
}

extern "C" void kernel_launch(void* const* d_in, const int* in_sizes, int n_in,
                              void* d_out, int out_size) {
    const float* x  = (const float*)d_in[0];
    const float* cb = (const float*)d_in[1];
    if (n_in >= 2 && in_sizes[0] == QL * KCODES * CD &&
        in_sizes[1] == NBATCH * CD * TT) {
        const float* tmp = x; x = cb; cb = tmp;
    }
    float* out = (float*)d_out;

    cudaFuncSetAttribute(vq_main_kernel,
                         cudaFuncAttributeMaxDynamicSharedMemorySize, SMEM_BYTES);

    cbnorm_kernel<<<(QL * KCODES * 32 + 255) / 256, 256>>>(cb);
    vq_main_kernel<<<NBLK, 256, SMEM_BYTES>>>(x, cb, out, out_size);
}